// round 3
// baseline (speedup 1.0000x reference)
#include <cuda_runtime.h>
#include <cuda_fp16.h>
#include <cstdint>
#include <cstddef>

// ---------------- problem constants ----------------
constexpr int NB     = 1024;   // batches
constexpr int NQC    = 32;     // queries per batch
constexpr int NDOC   = 2048;   // docs per batch
constexpr int DK     = 128;    // embedding dim
constexpr int TILE_M = 128;    // docs per tile (32 per warp)
constexpr int NTILES = NDOC / TILE_M;  // 16
constexpr int PITCH  = 272;    // fp16 row pitch (256B data + 16B pad, conflict-free)

// normalized queries (fp16), produced by qnorm_kernel (8 MB static)
__device__ __half g_qn[(size_t)NB * NQC * DK];

// ---------------- PTX helpers ----------------
__device__ __forceinline__ uint32_t smem_u32(const void* p) {
    uint32_t a;
    asm("{ .reg .u64 t; cvta.to.shared.u64 t, %1; cvt.u32.u64 %0, t; }" : "=r"(a) : "l"(p));
    return a;
}
// packs (lo, hi) -> f16x2 register (lo in low half)
__device__ __forceinline__ uint32_t pack_h2(float lo, float hi) {
    uint32_t r;
    asm("cvt.rn.f16x2.f32 %0, %1, %2;" : "=r"(r) : "f"(hi), "f"(lo));
    return r;
}
__device__ __forceinline__ uint32_t lds32(uint32_t a) {
    uint32_t v;
    asm volatile("ld.shared.b32 %0, [%1];" : "=r"(v) : "r"(a));
    return v;
}
__device__ __forceinline__ void sts64(uint32_t a, uint32_t r0, uint32_t r1) {
    asm volatile("st.shared.v2.b32 [%0], {%1,%2};" :: "r"(a), "r"(r0), "r"(r1) : "memory");
}
__device__ __forceinline__ void ldsm_x4(uint32_t* r, uint32_t a) {
    asm volatile("ldmatrix.sync.aligned.m8n8.x4.shared.b16 {%0,%1,%2,%3}, [%4];"
                 : "=r"(r[0]), "=r"(r[1]), "=r"(r[2]), "=r"(r[3]) : "r"(a));
}
__device__ __forceinline__ void mma16816(float* c, const uint32_t* a, const uint32_t* b) {
    asm volatile(
        "mma.sync.aligned.m16n8k16.row.col.f32.f16.f16.f32 "
        "{%0,%1,%2,%3}, {%4,%5,%6,%7}, {%8,%9}, {%0,%1,%2,%3};"
        : "+f"(c[0]), "+f"(c[1]), "+f"(c[2]), "+f"(c[3])
        : "r"(a[0]), "r"(a[1]), "r"(a[2]), "r"(a[3]), "r"(b[0]), "r"(b[1]));
}

// ---------------- kernel 0: normalize queries -> fp16 ----------------
__global__ void __launch_bounds__(128) qnorm_kernel(const float* __restrict__ q) {
    int row  = blockIdx.x * 4 + (threadIdx.x >> 5);   // [0, NB*NQC)
    int lane = threadIdx.x & 31;
    const float4 v = reinterpret_cast<const float4*>(q + (size_t)row * DK)[lane];
    float ss = v.x * v.x + v.y * v.y + v.z * v.z + v.w * v.w;
    #pragma unroll
    for (int o = 16; o; o >>= 1) ss += __shfl_xor_sync(0xFFFFFFFFu, ss, o);
    float rn = rsqrtf(fmaxf(ss, 1e-24f));
    __half2* dst = reinterpret_cast<__half2*>(g_qn + (size_t)row * DK);
    dst[lane * 2 + 0] = __floats2half2_rn(v.x * rn, v.y * rn);
    dst[lane * 2 + 1] = __floats2half2_rn(v.z * rn, v.w * rn);
}

// ---------------- kernel 1: streaming MaxSim ----------------
__global__ void __launch_bounds__(128, 4)
maxsim_kernel(const float* __restrict__ doc, float* __restrict__ out) {
    __shared__ __align__(16) char smA_raw[TILE_M * PITCH];  // fp16 doc tile (warp-private rows)
    __shared__ __align__(16) char smB_raw[NQC * PITCH];     // fp16 queries
    __shared__ float rnorm_s[TILE_M];
    __shared__ float red[128];

    const int b    = blockIdx.x;
    const int tid  = threadIdx.x;
    const int w    = tid >> 5;
    const int lane = tid & 31;

    const uint32_t smA = smem_u32(smA_raw);
    const uint32_t smB = smem_u32(smB_raw);

    // --- load normalized queries (fp16) into smB, pitch 272 ---
    {
        const __half* qb = g_qn + (size_t)b * NQC * DK;
        #pragma unroll
        for (int i = tid; i < NQC * 16; i += 128) {        // 16 x 16B chunks per row
            int r = i >> 4, c = i & 15;
            uint4 v = reinterpret_cast<const uint4*>(qb + r * DK)[c];
            *reinterpret_cast<uint4*>(smB_raw + r * PITCH + c * 16) = v;
        }
    }
    __syncthreads();

    float vmax[8];
    #pragma unroll
    for (int e = 0; e < 8; e++) vmax[e] = -1e30f;

    const float* dwarp = doc + ((size_t)b * NDOC + w * 32) * DK + lane * 4;

    for (int t = 0; t < NTILES; t++) {
        // ---- convert: warp w owns doc rows [w*32, w*32+32) of this tile ----
        // one coalesced LDG.128 per row (lane covers cols 4l..4l+3)
        const float* dt = dwarp + (size_t)t * TILE_M * DK;
        #pragma unroll
        for (int g = 0; g < 4; g++) {
            float4 v[8];
            #pragma unroll
            for (int r = 0; r < 8; r++)
                v[r] = *reinterpret_cast<const float4*>(dt + (g * 8 + r) * DK);
            #pragma unroll
            for (int r = 0; r < 8; r++) {
                int row = w * 32 + g * 8 + r;
                float ss = v[r].x * v[r].x + v[r].y * v[r].y +
                           v[r].z * v[r].z + v[r].w * v[r].w;
                #pragma unroll
                for (int o = 16; o; o >>= 1) ss += __shfl_xor_sync(0xFFFFFFFFu, ss, o);
                if (lane == 0) rnorm_s[row] = rsqrtf(fmaxf(ss, 1e-24f));
                sts64(smA + row * PITCH + lane * 8,
                      pack_h2(v[r].x, v[r].y), pack_h2(v[r].z, v[r].w));
            }
        }
        __syncwarp();   // smA rows + rnorm_s are warp-private: no CTA barrier needed

        // ---- HMMA: sim[32 docs x 32 queries] = A(f16) * B(f16)^T, fp32 acc ----
        float acc[2][4][4];
        #pragma unroll
        for (int m = 0; m < 2; m++)
            #pragma unroll
            for (int n = 0; n < 4; n++)
                #pragma unroll
                for (int i = 0; i < 4; i++) acc[m][n][i] = 0.f;

        #pragma unroll
        for (int kb = 0; kb < 8; kb++) {
            uint32_t bb[4][2];
            #pragma unroll
            for (int n = 0; n < 4; n++) {
                uint32_t ba = smB + (n * 8 + (lane >> 2)) * PITCH + kb * 32 + (lane & 3) * 4;
                bb[n][0] = lds32(ba);
                bb[n][1] = lds32(ba + 16);
            }
            #pragma unroll
            for (int m = 0; m < 2; m++) {
                uint32_t aa[4];
                ldsm_x4(aa, smA + (w * 32 + m * 16 + (lane & 15)) * PITCH
                               + kb * 32 + (lane & 16));
                #pragma unroll
                for (int n = 0; n < 4; n++) mma16816(acc[m][n], aa, bb[n]);
            }
        }

        // ---- epilogue: scale by 1/||d||, running max per query column ----
        #pragma unroll
        for (int m = 0; m < 2; m++) {
            float rn0 = rnorm_s[w * 32 + m * 16 + (lane >> 2)];
            float rn1 = rnorm_s[w * 32 + m * 16 + (lane >> 2) + 8];
            #pragma unroll
            for (int n = 0; n < 4; n++) {
                vmax[n * 2 + 0] = fmaxf(vmax[n * 2 + 0],
                                        fmaxf(acc[m][n][0] * rn0, acc[m][n][2] * rn1));
                vmax[n * 2 + 1] = fmaxf(vmax[n * 2 + 1],
                                        fmaxf(acc[m][n][1] * rn0, acc[m][n][3] * rn1));
            }
        }
        __syncwarp();   // all lanes done reading smA/rnorm before next tile overwrites
    }

    // ---- reduce: max over lanes sharing a query column (xor 4,8,16) ----
    #pragma unroll
    for (int e = 0; e < 8; e++) {
        vmax[e] = fmaxf(vmax[e], __shfl_xor_sync(0xFFFFFFFFu, vmax[e], 4));
        vmax[e] = fmaxf(vmax[e], __shfl_xor_sync(0xFFFFFFFFu, vmax[e], 8));
        vmax[e] = fmaxf(vmax[e], __shfl_xor_sync(0xFFFFFFFFu, vmax[e], 16));
    }
    if (lane < 4) {
        #pragma unroll
        for (int e = 0; e < 8; e++) {
            int col = (e >> 1) * 8 + lane * 2 + (e & 1);
            red[w * 32 + col] = vmax[e];
        }
    }
    __syncthreads();
    if (tid < 32) {
        float m = fmaxf(fmaxf(red[tid], red[32 + tid]),
                        fmaxf(red[64 + tid], red[96 + tid]));
        #pragma unroll
        for (int o = 16; o; o >>= 1) m += __shfl_xor_sync(0xFFFFFFFFu, m, o);
        if (tid == 0) out[b] = m;
    }
}

// ---------------- host launch ----------------
extern "C" void kernel_launch(void* const* d_in, const int* in_sizes, int n_in,
                              void* d_out, int out_size) {
    const float* q   = (const float*)d_in[0];   // [1024, 32, 128] f32
    const float* doc = (const float*)d_in[1];   // [1024, 2048, 128] f32
    float* out = (float*)d_out;                 // [1024] f32

    qnorm_kernel<<<(NB * NQC) / 4, 128>>>(q);
    maxsim_kernel<<<NB, 128>>>(doc, out);
}

// round 4
// speedup vs baseline: 1.5655x; 1.5655x over previous
#include <cuda_runtime.h>
#include <cuda_fp16.h>
#include <cstdint>
#include <cstddef>

// ---------------- problem constants ----------------
constexpr int NB     = 1024;   // batches
constexpr int NQC    = 32;     // queries per batch
constexpr int NDOC   = 2048;   // docs per batch
constexpr int DK     = 128;    // embedding dim
constexpr int TILE_M = 128;    // docs per tile (16 per warp)
constexpr int NTILES = NDOC / TILE_M;  // 16
constexpr int PITCH  = 272;    // fp16 row pitch (256B data + 16B pad)
constexpr int NW     = 8;      // warps per CTA
constexpr int NT     = NW * 32;

// ---------------- smem layout (bytes, dynamic) ----------------
constexpr int SM_B     = 0;                        // fp16 queries 32 x PITCH
constexpr int SM_RN    = NQC * PITCH;              // 8704: 128 f32 rnorms
constexpr int SM_RED   = SM_RN + TILE_M * 4;       // 9216: 256 f32 reduce scratch
constexpr int SM_A     = SM_RED + 256 * 4;         // 10240: fp16 A tile 128 x PITCH
constexpr int SM_STAGE = SM_A + TILE_M * PITCH;    // 45056 (512-aligned)
constexpr int STAGE_B  = TILE_M * 512;             // 65536 f32 stage per buffer
constexpr int SMEM_TOTAL = SM_STAGE + 2 * STAGE_B; // 176128

// normalized queries (fp16), produced by qnorm_kernel (8 MB static)
__device__ __half g_qn[(size_t)NB * NQC * DK];

// ---------------- PTX helpers ----------------
__device__ __forceinline__ uint32_t smem_u32(const void* p) {
    uint32_t a;
    asm("{ .reg .u64 t; cvta.to.shared.u64 t, %1; cvt.u32.u64 %0, t; }" : "=r"(a) : "l"(p));
    return a;
}
__device__ __forceinline__ uint32_t pack_h2(float lo, float hi) {
    uint32_t r;
    asm("cvt.rn.f16x2.f32 %0, %1, %2;" : "=r"(r) : "f"(hi), "f"(lo));
    return r;
}
__device__ __forceinline__ uint32_t lds32(uint32_t a) {
    uint32_t v;
    asm volatile("ld.shared.b32 %0, [%1];" : "=r"(v) : "r"(a));
    return v;
}
__device__ __forceinline__ float4 lds_v4(uint32_t a) {
    float4 v;
    asm volatile("ld.shared.v4.f32 {%0,%1,%2,%3}, [%4];"
                 : "=f"(v.x), "=f"(v.y), "=f"(v.z), "=f"(v.w) : "r"(a));
    return v;
}
__device__ __forceinline__ void sts64(uint32_t a, uint32_t r0, uint32_t r1) {
    asm volatile("st.shared.v2.b32 [%0], {%1,%2};" :: "r"(a), "r"(r0), "r"(r1) : "memory");
}
__device__ __forceinline__ void cp_async16(uint32_t sa, const void* g) {
    asm volatile("cp.async.cg.shared.global [%0], [%1], 16;" :: "r"(sa), "l"(g));
}
__device__ __forceinline__ void cp_commit() { asm volatile("cp.async.commit_group;" ::: "memory"); }
__device__ __forceinline__ void cp_wait1()  { asm volatile("cp.async.wait_group 1;" ::: "memory"); }
__device__ __forceinline__ void ldsm_x4(uint32_t* r, uint32_t a) {
    asm volatile("ldmatrix.sync.aligned.m8n8.x4.shared.b16 {%0,%1,%2,%3}, [%4];"
                 : "=r"(r[0]), "=r"(r[1]), "=r"(r[2]), "=r"(r[3]) : "r"(a));
}
__device__ __forceinline__ void mma16816(float* c, const uint32_t* a, const uint32_t* b) {
    asm volatile(
        "mma.sync.aligned.m16n8k16.row.col.f32.f16.f16.f32 "
        "{%0,%1,%2,%3}, {%4,%5,%6,%7}, {%8,%9}, {%0,%1,%2,%3};"
        : "+f"(c[0]), "+f"(c[1]), "+f"(c[2]), "+f"(c[3])
        : "r"(a[0]), "r"(a[1]), "r"(a[2]), "r"(a[3]), "r"(b[0]), "r"(b[1]));
}

// ---------------- kernel 0: normalize queries -> fp16 ----------------
__global__ void __launch_bounds__(128) qnorm_kernel(const float* __restrict__ q) {
    int row  = blockIdx.x * 4 + (threadIdx.x >> 5);   // [0, NB*NQC)
    int lane = threadIdx.x & 31;
    const float4 v = reinterpret_cast<const float4*>(q + (size_t)row * DK)[lane];
    float ss = v.x * v.x + v.y * v.y + v.z * v.z + v.w * v.w;
    #pragma unroll
    for (int o = 16; o; o >>= 1) ss += __shfl_xor_sync(0xFFFFFFFFu, ss, o);
    float rn = rsqrtf(fmaxf(ss, 1e-24f));
    __half2* dst = reinterpret_cast<__half2*>(g_qn + (size_t)row * DK);
    dst[lane * 2 + 0] = __floats2half2_rn(v.x * rn, v.y * rn);
    dst[lane * 2 + 1] = __floats2half2_rn(v.z * rn, v.w * rn);
}

// ---------------- kernel 1: streaming MaxSim (cp.async pipelined, warp-sync) ----------------
__global__ void __launch_bounds__(NT, 1)
maxsim_kernel(const float* __restrict__ doc, float* __restrict__ out) {
    extern __shared__ char smem[];
    const int b    = blockIdx.x;
    const int tid  = threadIdx.x;
    const int w    = tid >> 5;      // warp 0..7
    const int lane = tid & 31;

    const uint32_t sb  = smem_u32(smem);
    const uint32_t smB = sb + SM_B;
    const uint32_t smA = sb + SM_A;
    const uint32_t smS = sb + SM_STAGE;
    float* rnorm_s = reinterpret_cast<float*>(smem + SM_RN);
    float* red     = reinterpret_cast<float*>(smem + SM_RED);

    // --- load normalized queries (fp16) into smB ---
    {
        const __half* qb = g_qn + (size_t)b * NQC * DK;
        #pragma unroll
        for (int i = tid; i < NQC * 16; i += NT) {
            int r = i >> 4, c = i & 15;
            uint4 v = reinterpret_cast<const uint4*>(qb + r * DK)[c];
            *reinterpret_cast<uint4*>(smem + SM_B + r * PITCH + c * 16) = v;
        }
    }
    __syncthreads();

    // --- preload ALL B fragments into registers (64 regs): no B LDS in the loop ---
    uint32_t bf[8][4][2];
    #pragma unroll
    for (int kb = 0; kb < 8; kb++)
        #pragma unroll
        for (int n = 0; n < 4; n++) {
            uint32_t ba = smB + (n * 8 + (lane >> 2)) * PITCH + kb * 32 + (lane & 3) * 4;
            bf[kb][n][0] = lds32(ba);
            bf[kb][n][1] = lds32(ba + 16);
        }

    const char* dbase = reinterpret_cast<const char*>(doc) + (size_t)b * NDOC * DK * 4;

    // --- prologue: warp w streams rows {w, w+8, ..., w+120}; prefetch tiles 0,1 ---
    #pragma unroll
    for (int p = 0; p < 2; p++) {
        const char* g = dbase + (size_t)p * TILE_M * 512;
        uint32_t sdst = smS + p * STAGE_B;
        #pragma unroll
        for (int i = 0; i < 16; i++) {
            int row = w + 8 * i;
            cp_async16(sdst + row * 512 + lane * 16, g + row * 512 + lane * 16);
        }
        cp_commit();
    }

    float vmax[8];
    #pragma unroll
    for (int e = 0; e < 8; e++) vmax[e] = -1e30f;

    for (int t = 0; t < NTILES; t++) {
        cp_wait1();          // this thread's tile-t group complete
        __syncwarp();        // whole warp's tile-t rows visible warp-wide

        // --- convert: 16 warp-owned rows f32 -> fp16 A, exact fp32 norms ---
        uint32_t sstage = smS + (t & 1) * STAGE_B;
        #pragma unroll
        for (int i = 0; i < 16; i++) {
            float4 v = lds_v4(sstage + (w + 8 * i) * 512 + lane * 16);
            float ss = v.x * v.x + v.y * v.y + v.z * v.z + v.w * v.w;
            #pragma unroll
            for (int o = 16; o; o >>= 1) ss += __shfl_xor_sync(0xFFFFFFFFu, ss, o);
            if (lane == 0) rnorm_s[w * 16 + i] = rsqrtf(fmaxf(ss, 1e-24f));
            sts64(smA + (w * 16 + i) * PITCH + lane * 8,
                  pack_h2(v.x, v.y), pack_h2(v.z, v.w));
        }
        __syncwarp();        // stage reads done + A/rnorm visible warp-wide

        // --- prefetch tile t+2 into the stage buffer just consumed ---
        if (t + 2 < NTILES) {
            const char* g = dbase + (size_t)(t + 2) * TILE_M * 512;
            uint32_t sdst = smS + (t & 1) * STAGE_B;
            #pragma unroll
            for (int i = 0; i < 16; i++) {
                int row = w + 8 * i;
                cp_async16(sdst + row * 512 + lane * 16, g + row * 512 + lane * 16);
            }
        }
        cp_commit();         // unconditional: keeps wait_group accounting uniform

        // --- HMMA: sim[16 docs x 32 queries], fp32 acc ---
        float acc[4][4];
        #pragma unroll
        for (int n = 0; n < 4; n++)
            #pragma unroll
            for (int i = 0; i < 4; i++) acc[n][i] = 0.f;

        #pragma unroll
        for (int kb = 0; kb < 8; kb++) {
            uint32_t aa[4];
            ldsm_x4(aa, smA + (w * 16 + (lane & 15)) * PITCH + kb * 32 + (lane & 16));
            #pragma unroll
            for (int n = 0; n < 4; n++) mma16816(acc[n], aa, bf[kb][n]);
        }

        // --- epilogue: scale by 1/||d||, running max per query column ---
        float rn0 = rnorm_s[w * 16 + (lane >> 2)];
        float rn1 = rnorm_s[w * 16 + (lane >> 2) + 8];
        #pragma unroll
        for (int n = 0; n < 4; n++) {
            vmax[n * 2 + 0] = fmaxf(vmax[n * 2 + 0],
                                    fmaxf(acc[n][0] * rn0, acc[n][2] * rn1));
            vmax[n * 2 + 1] = fmaxf(vmax[n * 2 + 1],
                                    fmaxf(acc[n][1] * rn0, acc[n][3] * rn1));
        }
        __syncwarp();        // all lanes done reading A/rnorm before next overwrite
    }

    // ---- reduce: max over lanes sharing a query column (xor 4,8,16) ----
    #pragma unroll
    for (int e = 0; e < 8; e++) {
        vmax[e] = fmaxf(vmax[e], __shfl_xor_sync(0xFFFFFFFFu, vmax[e], 4));
        vmax[e] = fmaxf(vmax[e], __shfl_xor_sync(0xFFFFFFFFu, vmax[e], 8));
        vmax[e] = fmaxf(vmax[e], __shfl_xor_sync(0xFFFFFFFFu, vmax[e], 16));
    }
    if (lane < 4) {
        #pragma unroll
        for (int e = 0; e < 8; e++) {
            int col = (e >> 1) * 8 + lane * 2 + (e & 1);
            red[w * 32 + col] = vmax[e];
        }
    }
    __syncthreads();
    if (tid < 32) {
        float m = red[tid];
        #pragma unroll
        for (int ww = 1; ww < NW; ww++) m = fmaxf(m, red[ww * 32 + tid]);
        #pragma unroll
        for (int o = 16; o; o >>= 1) m += __shfl_xor_sync(0xFFFFFFFFu, m, o);
        if (tid == 0) out[b] = m;
    }
}

// ---------------- host launch ----------------
extern "C" void kernel_launch(void* const* d_in, const int* in_sizes, int n_in,
                              void* d_out, int out_size) {
    const float* q   = (const float*)d_in[0];   // [1024, 32, 128] f32
    const float* doc = (const float*)d_in[1];   // [1024, 2048, 128] f32
    float* out = (float*)d_out;                 // [1024] f32

    cudaFuncSetAttribute(maxsim_kernel,
                         cudaFuncAttributeMaxDynamicSharedMemorySize, SMEM_TOTAL);

    qnorm_kernel<<<(NB * NQC) / 4, 128>>>(q);
    maxsim_kernel<<<NB, NT, SMEM_TOTAL>>>(doc, out);
}

// round 5
// speedup vs baseline: 2.7344x; 1.7467x over previous
#include <cuda_runtime.h>
#include <cuda_fp16.h>
#include <cstdint>
#include <cstddef>

// ---------------- problem constants ----------------
constexpr int NB     = 1024;   // batches
constexpr int NQC    = 32;     // queries per batch
constexpr int NDOC   = 2048;   // docs per batch
constexpr int DK     = 128;    // embedding dim
constexpr int TILE_M = 128;    // docs per tile (8 per warp)
constexpr int NTILES = NDOC / TILE_M;  // 16
constexpr int PITCH  = 272;    // fp16 row pitch (256B data + 16B pad)
constexpr int NW     = 16;     // warps per CTA
constexpr int NT     = NW * 32;  // 512 threads

// ---------------- smem layout (bytes, dynamic) ----------------
constexpr int SM_B     = 0;                        // fp16 queries 32 x PITCH
constexpr int SM_RN    = NQC * PITCH;              // 8704: 128 f32 rnorms
constexpr int SM_RED   = SM_RN + TILE_M * 4;       // 9216: 512 f32 reduce scratch
constexpr int SM_A     = SM_RED + NT * 4;          // 11264: fp16 A tile 128 x PITCH
constexpr int SM_STAGE = SM_A + TILE_M * PITCH;    // 46080 (512-aligned)
constexpr int STAGE_B  = TILE_M * 512;             // 65536 f32 stage per buffer
constexpr int SMEM_TOTAL = SM_STAGE + 2 * STAGE_B; // 177152

// normalized queries (fp16), produced by qnorm_kernel (8 MB static)
__device__ __half g_qn[(size_t)NB * NQC * DK];

// ---------------- PTX helpers ----------------
__device__ __forceinline__ uint32_t smem_u32(const void* p) {
    uint32_t a;
    asm("{ .reg .u64 t; cvta.to.shared.u64 t, %1; cvt.u32.u64 %0, t; }" : "=r"(a) : "l"(p));
    return a;
}
__device__ __forceinline__ uint32_t pack_h2(float lo, float hi) {
    uint32_t r;
    asm("cvt.rn.f16x2.f32 %0, %1, %2;" : "=r"(r) : "f"(hi), "f"(lo));
    return r;
}
__device__ __forceinline__ uint32_t lds32(uint32_t a) {
    uint32_t v;
    asm volatile("ld.shared.b32 %0, [%1];" : "=r"(v) : "r"(a));
    return v;
}
__device__ __forceinline__ float4 lds_v4(uint32_t a) {
    float4 v;
    asm volatile("ld.shared.v4.f32 {%0,%1,%2,%3}, [%4];"
                 : "=f"(v.x), "=f"(v.y), "=f"(v.z), "=f"(v.w) : "r"(a));
    return v;
}
__device__ __forceinline__ void sts64(uint32_t a, uint32_t r0, uint32_t r1) {
    asm volatile("st.shared.v2.b32 [%0], {%1,%2};" :: "r"(a), "r"(r0), "r"(r1) : "memory");
}
__device__ __forceinline__ void cp_async16(uint32_t sa, const void* g) {
    asm volatile("cp.async.cg.shared.global [%0], [%1], 16;" :: "r"(sa), "l"(g));
}
__device__ __forceinline__ void cp_commit() { asm volatile("cp.async.commit_group;" ::: "memory"); }
__device__ __forceinline__ void cp_wait1()  { asm volatile("cp.async.wait_group 1;" ::: "memory"); }
__device__ __forceinline__ void ldsm_x4(uint32_t* r, uint32_t a) {
    asm volatile("ldmatrix.sync.aligned.m8n8.x4.shared.b16 {%0,%1,%2,%3}, [%4];"
                 : "=r"(r[0]), "=r"(r[1]), "=r"(r[2]), "=r"(r[3]) : "r"(a));
}
__device__ __forceinline__ void mma16816(float* c, const uint32_t* a, const uint32_t* b) {
    asm volatile(
        "mma.sync.aligned.m16n8k16.row.col.f32.f16.f16.f32 "
        "{%0,%1,%2,%3}, {%4,%5,%6,%7}, {%8,%9}, {%0,%1,%2,%3};"
        : "+f"(c[0]), "+f"(c[1]), "+f"(c[2]), "+f"(c[3])
        : "r"(a[0]), "r"(a[1]), "r"(a[2]), "r"(a[3]), "r"(b[0]), "r"(b[1]));
}

// ---------------- kernel 0: normalize queries -> fp16 ----------------
__global__ void __launch_bounds__(128) qnorm_kernel(const float* __restrict__ q) {
    int row  = blockIdx.x * 4 + (threadIdx.x >> 5);   // [0, NB*NQC)
    int lane = threadIdx.x & 31;
    const float4 v = reinterpret_cast<const float4*>(q + (size_t)row * DK)[lane];
    float ss = v.x * v.x + v.y * v.y + v.z * v.z + v.w * v.w;
    #pragma unroll
    for (int o = 16; o; o >>= 1) ss += __shfl_xor_sync(0xFFFFFFFFu, ss, o);
    float rn = rsqrtf(fmaxf(ss, 1e-24f));
    __half2* dst = reinterpret_cast<__half2*>(g_qn + (size_t)row * DK);
    dst[lane * 2 + 0] = __floats2half2_rn(v.x * rn, v.y * rn);
    dst[lane * 2 + 1] = __floats2half2_rn(v.z * rn, v.w * rn);
}

// ---------------- kernel 1: streaming MaxSim (512 thr, warp-sync mainloop) ----------------
__global__ void __launch_bounds__(NT, 1)
maxsim_kernel(const float* __restrict__ doc, float* __restrict__ out) {
    extern __shared__ char smem[];
    const int b    = blockIdx.x;
    const int tid  = threadIdx.x;
    const int w    = tid >> 5;      // warp 0..15, owns doc rows [w*8, w*8+8) of each tile
    const int lane = tid & 31;

    const uint32_t sb  = smem_u32(smem);
    const uint32_t smB = sb + SM_B;
    const uint32_t smA = sb + SM_A;
    const uint32_t smS = sb + SM_STAGE;
    float* rnorm_s = reinterpret_cast<float*>(smem + SM_RN);
    float* red     = reinterpret_cast<float*>(smem + SM_RED);

    // --- load normalized queries (fp16) into smB ---
    {
        const __half* qb = g_qn + (size_t)b * NQC * DK;
        #pragma unroll
        for (int i = tid; i < NQC * 16; i += NT) {
            int r = i >> 4, c = i & 15;
            uint4 v = reinterpret_cast<const uint4*>(qb + r * DK)[c];
            *reinterpret_cast<uint4*>(smem + SM_B + r * PITCH + c * 16) = v;
        }
    }
    __syncthreads();

    // --- preload ALL B fragments into registers (64 regs): no B LDS in the loop ---
    uint32_t bf[8][4][2];
    #pragma unroll
    for (int kb = 0; kb < 8; kb++)
        #pragma unroll
        for (int n = 0; n < 4; n++) {
            uint32_t ba = smB + (n * 8 + (lane >> 2)) * PITCH + kb * 32 + (lane & 3) * 4;
            bf[kb][n][0] = lds32(ba);
            bf[kb][n][1] = lds32(ba + 16);
        }

    const char* dbase = reinterpret_cast<const char*>(doc) + (size_t)b * NDOC * DK * 4;
    const uint32_t soff = (w * 8) * 512 + lane * 16;   // warp's stage sub-block offset

    // --- prologue: prefetch tiles 0,1 (8 rows x 512B per warp each) ---
    #pragma unroll
    for (int p = 0; p < 2; p++) {
        const char* g = dbase + (size_t)p * TILE_M * 512 + soff;
        uint32_t sdst = smS + p * STAGE_B + soff;
        #pragma unroll
        for (int r = 0; r < 8; r++)
            cp_async16(sdst + r * 512, g + r * 512);
        cp_commit();
    }

    float vmax[8];
    #pragma unroll
    for (int e = 0; e < 8; e++) vmax[e] = -1e30f;

    for (int t = 0; t < NTILES; t++) {
        cp_wait1();   // each thread reads only the 16B/row it copied itself: no syncwarp needed

        const uint32_t sstage = smS + (t & 1) * STAGE_B + soff;
        const bool pf = (t + 2 < NTILES);
        const char* gpf = dbase + (size_t)(t + 2) * TILE_M * 512 + soff;
        const uint32_t spf = sstage;   // same buffer being freed

        // --- convert 8 warp-owned rows in 2 groups of 4; fire t+2 prefetch between
        //     the stage reads and the math so the fetch starts early ---
        #pragma unroll
        for (int g = 0; g < 2; g++) {
            float4 v[4];
            #pragma unroll
            for (int r = 0; r < 4; r++)
                v[r] = lds_v4(sstage + (g * 4 + r) * 512);
            if (pf) {
                #pragma unroll
                for (int r = 0; r < 4; r++)
                    cp_async16(spf + (g * 4 + r) * 512, gpf + (g * 4 + r) * 512);
            }
            #pragma unroll
            for (int r = 0; r < 4; r++) {
                int row = w * 8 + g * 4 + r;
                float ss = v[r].x * v[r].x + v[r].y * v[r].y +
                           v[r].z * v[r].z + v[r].w * v[r].w;
                #pragma unroll
                for (int o = 16; o; o >>= 1) ss += __shfl_xor_sync(0xFFFFFFFFu, ss, o);
                if (lane == 0) rnorm_s[row] = rsqrtf(fmaxf(ss, 1e-24f));
                sts64(smA + row * PITCH + lane * 8,
                      pack_h2(v[r].x, v[r].y), pack_h2(v[r].z, v[r].w));
            }
        }
        cp_commit();   // one group per iteration keeps wait accounting uniform
        __syncwarp();  // A rows + rnorm visible warp-wide before ldmatrix

        // --- HMMA: 8 real doc rows x 32 queries (upper fragment half duplicated) ---
        float acc[4][4];
        #pragma unroll
        for (int n = 0; n < 4; n++)
            #pragma unroll
            for (int i = 0; i < 4; i++) acc[n][i] = 0.f;

        #pragma unroll
        for (int kb = 0; kb < 8; kb++) {
            uint32_t aa[4];
            ldsm_x4(aa, smA + (w * 8 + (lane & 7)) * PITCH + kb * 32 + (lane & 16));
            #pragma unroll
            for (int n = 0; n < 4; n++) mma16816(acc[n], aa, bf[kb][n]);
        }

        // --- epilogue: only c0,c1 are real (rows 0-7); scale by 1/||d||, running max ---
        float rn0 = rnorm_s[w * 8 + (lane >> 2)];
        #pragma unroll
        for (int n = 0; n < 4; n++) {
            vmax[n * 2 + 0] = fmaxf(vmax[n * 2 + 0], acc[n][0] * rn0);
            vmax[n * 2 + 1] = fmaxf(vmax[n * 2 + 1], acc[n][1] * rn0);
        }
        __syncwarp();  // all lanes done reading A/rnorm before next overwrite
    }

    // ---- reduce: max over lanes sharing a query column (xor 4,8,16) ----
    #pragma unroll
    for (int e = 0; e < 8; e++) {
        vmax[e] = fmaxf(vmax[e], __shfl_xor_sync(0xFFFFFFFFu, vmax[e], 4));
        vmax[e] = fmaxf(vmax[e], __shfl_xor_sync(0xFFFFFFFFu, vmax[e], 8));
        vmax[e] = fmaxf(vmax[e], __shfl_xor_sync(0xFFFFFFFFu, vmax[e], 16));
    }
    if (lane < 4) {
        #pragma unroll
        for (int e = 0; e < 8; e++) {
            int col = (e >> 1) * 8 + lane * 2 + (e & 1);
            red[w * 32 + col] = vmax[e];
        }
    }
    __syncthreads();
    if (tid < 32) {
        float m = red[tid];
        #pragma unroll
        for (int ww = 1; ww < NW; ww++) m = fmaxf(m, red[ww * 32 + tid]);
        #pragma unroll
        for (int o = 16; o; o >>= 1) m += __shfl_xor_sync(0xFFFFFFFFu, m, o);
        if (tid == 0) out[b] = m;
    }
}

// ---------------- host launch ----------------
extern "C" void kernel_launch(void* const* d_in, const int* in_sizes, int n_in,
                              void* d_out, int out_size) {
    const float* q   = (const float*)d_in[0];   // [1024, 32, 128] f32
    const float* doc = (const float*)d_in[1];   // [1024, 2048, 128] f32
    float* out = (float*)d_out;                 // [1024] f32

    cudaFuncSetAttribute(maxsim_kernel,
                         cudaFuncAttributeMaxDynamicSharedMemorySize, SMEM_TOTAL);

    qnorm_kernel<<<(NB * NQC) / 4, 128>>>(q);
    maxsim_kernel<<<NB, NT, SMEM_TOTAL>>>(doc, out);
}

// round 7
// speedup vs baseline: 2.9996x; 1.0970x over previous
#include <cuda_runtime.h>
#include <cuda_fp16.h>
#include <cstdint>
#include <cstddef>

// ---------------- problem constants ----------------
constexpr int NB     = 1024;   // batches
constexpr int NQC    = 32;     // queries per batch
constexpr int NDOC   = 2048;   // docs per batch
constexpr int DK     = 128;    // embedding dim
constexpr int TILE_M = 64;     // docs per tile (8 per warp)
constexpr int NTILES = NDOC / TILE_M;  // 32
constexpr int PITCH  = 272;    // fp16 row pitch (256B data + 16B pad)
constexpr int NW     = 8;      // warps per CTA
constexpr int NT     = NW * 32;  // 256 threads

// ---------------- smem layout (bytes, dynamic) ----------------
constexpr int SM_B     = 0;                        // fp16 queries 32 x PITCH
constexpr int SM_RN    = NQC * PITCH;              // 8704: 64 f32 rnorms
constexpr int SM_RED   = SM_RN + TILE_M * 4;       // 8960: 256 f32 reduce scratch
constexpr int SM_A     = SM_RED + NT * 4;          // 9984: fp16 A tile 64 x PITCH
constexpr int SM_STAGE = ((SM_A + TILE_M * PITCH + 511) / 512) * 512;  // 27648
constexpr int STAGE_B  = TILE_M * 512;             // 32768 f32 stage per buffer
constexpr int SMEM_TOTAL = SM_STAGE + 2 * STAGE_B; // 93184  (x2 CTAs = 186 KB/SM)

// ---------------- PTX helpers ----------------
__device__ __forceinline__ uint32_t smem_u32(const void* p) {
    uint32_t a;
    asm("{ .reg .u64 t; cvta.to.shared.u64 t, %1; cvt.u32.u64 %0, t; }" : "=r"(a) : "l"(p));
    return a;
}
__device__ __forceinline__ uint32_t pack_h2(float lo, float hi) {
    uint32_t r;
    asm("cvt.rn.f16x2.f32 %0, %1, %2;" : "=r"(r) : "f"(hi), "f"(lo));
    return r;
}
__device__ __forceinline__ uint32_t lds32(uint32_t a) {
    uint32_t v;
    asm volatile("ld.shared.b32 %0, [%1];" : "=r"(v) : "r"(a));
    return v;
}
__device__ __forceinline__ float4 lds_v4(uint32_t a) {
    float4 v;
    asm volatile("ld.shared.v4.f32 {%0,%1,%2,%3}, [%4];"
                 : "=f"(v.x), "=f"(v.y), "=f"(v.z), "=f"(v.w) : "r"(a));
    return v;
}
__device__ __forceinline__ void sts64(uint32_t a, uint32_t r0, uint32_t r1) {
    asm volatile("st.shared.v2.b32 [%0], {%1,%2};" :: "r"(a), "r"(r0), "r"(r1) : "memory");
}
__device__ __forceinline__ void cp_async16(uint32_t sa, const void* g) {
    asm volatile("cp.async.cg.shared.global [%0], [%1], 16;" :: "r"(sa), "l"(g));
}
__device__ __forceinline__ void cp_commit() { asm volatile("cp.async.commit_group;" ::: "memory"); }
__device__ __forceinline__ void cp_wait1()  { asm volatile("cp.async.wait_group 1;" ::: "memory"); }
__device__ __forceinline__ void ldsm_x4(uint32_t* r, uint32_t a) {
    asm volatile("ldmatrix.sync.aligned.m8n8.x4.shared.b16 {%0,%1,%2,%3}, [%4];"
                 : "=r"(r[0]), "=r"(r[1]), "=r"(r[2]), "=r"(r[3]) : "r"(a));
}
__device__ __forceinline__ void mma16816(float* c, const uint32_t* a, const uint32_t* b) {
    asm volatile(
        "mma.sync.aligned.m16n8k16.row.col.f32.f16.f16.f32 "
        "{%0,%1,%2,%3}, {%4,%5,%6,%7}, {%8,%9}, {%0,%1,%2,%3};"
        : "+f"(c[0]), "+f"(c[1]), "+f"(c[2]), "+f"(c[3])
        : "r"(a[0]), "r"(a[1]), "r"(a[2]), "r"(a[3]), "r"(b[0]), "r"(b[1]));
}

// ---------------- fused kernel: qnorm + streaming MaxSim ----------------
__global__ void __launch_bounds__(NT, 2)
maxsim_kernel(const float* __restrict__ q, const float* __restrict__ doc,
              float* __restrict__ out) {
    extern __shared__ char smem[];
    const int b    = blockIdx.x;
    const int tid  = threadIdx.x;
    const int w    = tid >> 5;      // warp 0..7, owns doc rows [w*8, w*8+8) of each tile
    const int lane = tid & 31;

    const uint32_t sb  = smem_u32(smem);
    const uint32_t smB = sb + SM_B;
    const uint32_t smA = sb + SM_A;
    const uint32_t smS = sb + SM_STAGE;
    float* rnorm_s = reinterpret_cast<float*>(smem + SM_RN);
    float* red     = reinterpret_cast<float*>(smem + SM_RED);

    const char* dbase = reinterpret_cast<const char*>(doc) + (size_t)b * NDOC * DK * 4;
    const uint32_t soff = (w * 8) * 512 + lane * 16;   // warp's stage sub-block offset

    // --- prologue FIRST: get tiles 0,1 in flight before doing query math ---
    #pragma unroll
    for (int p = 0; p < 2; p++) {
        const char* g = dbase + (size_t)p * TILE_M * 512 + soff;
        uint32_t sdst = smS + p * STAGE_B + soff;
        #pragma unroll
        for (int r = 0; r < 8; r++)
            cp_async16(sdst + r * 512, g + r * 512);
        cp_commit();
    }

    // --- normalize this batch's 32 queries -> fp16 smB (warp w does rows w*4..w*4+3) ---
    {
        const float* qb = q + (size_t)b * NQC * DK;
        #pragma unroll
        for (int i = 0; i < 4; i++) {
            int r = w * 4 + i;
            float4 v = reinterpret_cast<const float4*>(qb + (size_t)r * DK)[lane];
            float ss = v.x * v.x + v.y * v.y + v.z * v.z + v.w * v.w;
            #pragma unroll
            for (int o = 16; o; o >>= 1) ss += __shfl_xor_sync(0xFFFFFFFFu, ss, o);
            float rn = rsqrtf(fmaxf(ss, 1e-24f));
            sts64(smB + r * PITCH + lane * 8,
                  pack_h2(v.x * rn, v.y * rn), pack_h2(v.z * rn, v.w * rn));
        }
    }
    __syncthreads();

    // --- preload ALL B fragments into registers (64 regs): no B LDS in the loop ---
    uint32_t bf[8][4][2];
    #pragma unroll
    for (int kb = 0; kb < 8; kb++)
        #pragma unroll
        for (int n = 0; n < 4; n++) {
            uint32_t ba = smB + (n * 8 + (lane >> 2)) * PITCH + kb * 32 + (lane & 3) * 4;
            bf[kb][n][0] = lds32(ba);
            bf[kb][n][1] = lds32(ba + 16);
        }

    float vmax[8];
    #pragma unroll
    for (int e = 0; e < 8; e++) vmax[e] = -1e30f;

    for (int t = 0; t < NTILES; t++) {
        cp_wait1();   // each thread reads only the 16B/row it copied itself

        const uint32_t sstage = smS + (t & 1) * STAGE_B + soff;
        const bool pf = (t + 2 < NTILES);
        const char* gpf = dbase + (size_t)(t + 2) * TILE_M * 512 + soff;

        // --- convert 8 warp-owned rows in 2 groups of 4; fire t+2 prefetch between
        //     the stage reads and the math so the fetch starts early ---
        #pragma unroll
        for (int g = 0; g < 2; g++) {
            float4 v[4];
            #pragma unroll
            for (int r = 0; r < 4; r++)
                v[r] = lds_v4(sstage + (g * 4 + r) * 512);
            if (pf) {
                #pragma unroll
                for (int r = 0; r < 4; r++)
                    cp_async16(sstage + (g * 4 + r) * 512, gpf + (g * 4 + r) * 512);
            }
            #pragma unroll
            for (int r = 0; r < 4; r++) {
                int row = w * 8 + g * 4 + r;
                float ss = v[r].x * v[r].x + v[r].y * v[r].y +
                           v[r].z * v[r].z + v[r].w * v[r].w;
                #pragma unroll
                for (int o = 16; o; o >>= 1) ss += __shfl_xor_sync(0xFFFFFFFFu, ss, o);
                if (lane == 0) rnorm_s[row] = rsqrtf(fmaxf(ss, 1e-24f));
                sts64(smA + row * PITCH + lane * 8,
                      pack_h2(v[r].x, v[r].y), pack_h2(v[r].z, v[r].w));
            }
        }
        cp_commit();   // one group per iteration keeps wait accounting uniform
        __syncwarp();  // A rows + rnorm visible warp-wide before ldmatrix

        // --- HMMA: 8 real doc rows x 32 queries (upper fragment half duplicated) ---
        float acc[4][4];
        #pragma unroll
        for (int n = 0; n < 4; n++)
            #pragma unroll
            for (int i = 0; i < 4; i++) acc[n][i] = 0.f;

        #pragma unroll
        for (int kb = 0; kb < 8; kb++) {
            uint32_t aa[4];
            ldsm_x4(aa, smA + (w * 8 + (lane & 7)) * PITCH + kb * 32 + (lane & 16));
            #pragma unroll
            for (int n = 0; n < 4; n++) mma16816(acc[n], aa, bf[kb][n]);
        }

        // --- epilogue: only c0,c1 are real (rows 0-7); scale by 1/||d||, running max ---
        float rn0 = rnorm_s[w * 8 + (lane >> 2)];
        #pragma unroll
        for (int n = 0; n < 4; n++) {
            vmax[n * 2 + 0] = fmaxf(vmax[n * 2 + 0], acc[n][0] * rn0);
            vmax[n * 2 + 1] = fmaxf(vmax[n * 2 + 1], acc[n][1] * rn0);
        }
        __syncwarp();  // all lanes done reading A/rnorm before next overwrite
    }

    // ---- reduce: max over lanes sharing a query column (xor 4,8,16) ----
    #pragma unroll
    for (int e = 0; e < 8; e++) {
        vmax[e] = fmaxf(vmax[e], __shfl_xor_sync(0xFFFFFFFFu, vmax[e], 4));
        vmax[e] = fmaxf(vmax[e], __shfl_xor_sync(0xFFFFFFFFu, vmax[e], 8));
        vmax[e] = fmaxf(vmax[e], __shfl_xor_sync(0xFFFFFFFFu, vmax[e], 16));
    }
    if (lane < 4) {
        #pragma unroll
        for (int e = 0; e < 8; e++) {
            int col = (e >> 1) * 8 + lane * 2 + (e & 1);
            red[w * 32 + col] = vmax[e];
        }
    }
    __syncthreads();
    if (tid < 32) {
        float m = red[tid];
        #pragma unroll
        for (int ww = 1; ww < NW; ww++) m = fmaxf(m, red[ww * 32 + tid]);
        #pragma unroll
        for (int o = 16; o; o >>= 1) m += __shfl_xor_sync(0xFFFFFFFFu, m, o);
        if (tid == 0) out[b] = m;
    }
}

// ---------------- host launch ----------------
extern "C" void kernel_launch(void* const* d_in, const int* in_sizes, int n_in,
                              void* d_out, int out_size) {
    const float* q   = (const float*)d_in[0];   // [1024, 32, 128] f32
    const float* doc = (const float*)d_in[1];   // [1024, 2048, 128] f32
    float* out = (float*)d_out;                 // [1024] f32

    cudaFuncSetAttribute(maxsim_kernel,
                         cudaFuncAttributeMaxDynamicSharedMemorySize, SMEM_TOTAL);

    maxsim_kernel<<<NB, NT, SMEM_TOTAL>>>(q, doc, out);
}

// round 8
// speedup vs baseline: 3.0411x; 1.0138x over previous
#include <cuda_runtime.h>
#include <cuda_fp16.h>
#include <cstdint>
#include <cstddef>

// ---------------- problem constants ----------------
constexpr int NB     = 1024;   // batches
constexpr int NQC    = 32;     // queries per batch
constexpr int NDOC   = 2048;   // docs per batch
constexpr int DK     = 128;    // embedding dim
constexpr int TILE_M = 64;     // docs per tile (8 per warp)
constexpr int NTILES = NDOC / TILE_M;  // 32
constexpr int PITCH  = 272;    // fp16 B row pitch
constexpr int SPITCH = 544;    // f32 stage row pitch (512 + 32 pad)
constexpr int NW     = 8;      // warps per CTA
constexpr int NT     = NW * 32;  // 256 threads
constexpr int NSTG   = 3;      // pipeline depth

// ---------------- smem layout (bytes, dynamic) ----------------
constexpr int SM_B     = 0;                        // fp16 queries 32 x PITCH = 8704
constexpr int SM_RED   = NQC * PITCH;              // 8704: 256 f32 reduce scratch
constexpr int SM_STAGE = SM_RED + NT * 4;          // 9728
constexpr int STAGE_B  = TILE_M * SPITCH;          // 34816 per buffer
constexpr int SMEM_TOTAL = SM_STAGE + NSTG * STAGE_B;  // 114176 (x2 CTAs/SM)

// ---------------- PTX helpers ----------------
__device__ __forceinline__ uint32_t smem_u32(const void* p) {
    uint32_t a;
    asm("{ .reg .u64 t; cvta.to.shared.u64 t, %1; cvt.u32.u64 %0, t; }" : "=r"(a) : "l"(p));
    return a;
}
__device__ __forceinline__ uint32_t pack_h2(float lo, float hi) {
    uint32_t r;
    asm("cvt.rn.f16x2.f32 %0, %1, %2;" : "=r"(r) : "f"(hi), "f"(lo));
    return r;
}
__device__ __forceinline__ uint32_t lds32(uint32_t a) {
    uint32_t v;
    asm volatile("ld.shared.b32 %0, [%1];" : "=r"(v) : "r"(a));
    return v;
}
__device__ __forceinline__ float2 lds_v2(uint32_t a) {
    float2 v;
    asm volatile("ld.shared.v2.f32 {%0,%1}, [%2];" : "=f"(v.x), "=f"(v.y) : "r"(a));
    return v;
}
__device__ __forceinline__ void sts64(uint32_t a, uint32_t r0, uint32_t r1) {
    asm volatile("st.shared.v2.b32 [%0], {%1,%2};" :: "r"(a), "r"(r0), "r"(r1) : "memory");
}
__device__ __forceinline__ void cp_async16(uint32_t sa, const void* g) {
    asm volatile("cp.async.cg.shared.global [%0], [%1], 16;" :: "r"(sa), "l"(g));
}
__device__ __forceinline__ void cp_commit() { asm volatile("cp.async.commit_group;" ::: "memory"); }
__device__ __forceinline__ void cp_wait2()  { asm volatile("cp.async.wait_group 2;" ::: "memory"); }
__device__ __forceinline__ void mma16816(float* c, const uint32_t* a, const uint32_t* b) {
    asm volatile(
        "mma.sync.aligned.m16n8k16.row.col.f32.f16.f16.f32 "
        "{%0,%1,%2,%3}, {%4,%5,%6,%7}, {%8,%9}, {%0,%1,%2,%3};"
        : "+f"(c[0]), "+f"(c[1]), "+f"(c[2]), "+f"(c[3])
        : "r"(a[0]), "r"(a[1]), "r"(a[2]), "r"(a[3]), "r"(b[0]), "r"(b[1]));
}

// ---------------- fused kernel: qnorm + streaming MaxSim ----------------
__global__ void __launch_bounds__(NT, 2)
maxsim_kernel(const float* __restrict__ q, const float* __restrict__ doc,
              float* __restrict__ out) {
    extern __shared__ char smem[];
    const int b    = blockIdx.x;
    const int tid  = threadIdx.x;
    const int w    = tid >> 5;      // warp 0..7, owns doc rows [w*8, w*8+8) of each tile
    const int lane = tid & 31;

    const uint32_t sb  = smem_u32(smem);
    const uint32_t smB = sb + SM_B;
    const uint32_t smS = sb + SM_STAGE;
    float* red = reinterpret_cast<float*>(smem + SM_RED);

    const char* dbase = reinterpret_cast<const char*>(doc) + (size_t)b * NDOC * DK * 4;
    // warp's cp.async offsets: thread writes rows w*8+r at byte col lane*16
    const uint32_t s_w_base = (w * 8) * SPITCH + lane * 16;
    const size_t   g_w_base = (size_t)(w * 8) * 512 + lane * 16;
    // thread's fragment-read base: row w*8+(lane>>2), byte col (lane&3)*8
    const uint32_t s_r_base = (w * 8 + (lane >> 2)) * SPITCH + (lane & 3) * 8;

    // --- prologue FIRST: get tiles 0..2 in flight before query math ---
    #pragma unroll
    for (int p = 0; p < NSTG; p++) {
        const char* g = dbase + (size_t)p * TILE_M * 512 + g_w_base;
        uint32_t sdst = smS + p * STAGE_B + s_w_base;
        #pragma unroll
        for (int r = 0; r < 8; r++)
            cp_async16(sdst + r * SPITCH, g + r * 512);
        cp_commit();
    }

    // --- normalize this batch's 32 queries -> fp16 smB (warp w does rows w*4..w*4+3) ---
    {
        const float* qb = q + (size_t)b * NQC * DK;
        #pragma unroll
        for (int i = 0; i < 4; i++) {
            int r = w * 4 + i;
            float4 v = reinterpret_cast<const float4*>(qb + (size_t)r * DK)[lane];
            float ss = v.x * v.x + v.y * v.y + v.z * v.z + v.w * v.w;
            #pragma unroll
            for (int o = 16; o; o >>= 1) ss += __shfl_xor_sync(0xFFFFFFFFu, ss, o);
            float rn = rsqrtf(fmaxf(ss, 1e-24f));
            sts64(smB + r * PITCH + lane * 8,
                  pack_h2(v.x * rn, v.y * rn), pack_h2(v.z * rn, v.w * rn));
        }
    }
    __syncthreads();

    // --- preload ALL B fragments into registers (64 regs): no B LDS in the loop ---
    uint32_t bf[8][4][2];
    #pragma unroll
    for (int kb = 0; kb < 8; kb++)
        #pragma unroll
        for (int n = 0; n < 4; n++) {
            uint32_t ba = smB + (n * 8 + (lane >> 2)) * PITCH + kb * 32 + (lane & 3) * 4;
            bf[kb][n][0] = lds32(ba);
            bf[kb][n][1] = lds32(ba + 16);
        }

    float vmax[8];
    #pragma unroll
    for (int e = 0; e < 8; e++) vmax[e] = -1e30f;

    for (int t = 0; t < NTILES; t++) {
        cp_wait2();      // tile t's group complete (<=2 newer pending)
        __syncwarp();    // warp-wide visibility of warp's rows

        const uint32_t buf = (uint32_t)(t % NSTG) * STAGE_B;
        const uint32_t trd = smS + buf + s_r_base;

        // --- read fragment elements straight from f32 stage; convert in registers ---
        uint32_t af0[8], af1[8];
        float ss = 0.f;
        #pragma unroll
        for (int kb = 0; kb < 8; kb++) {
            float2 p0 = lds_v2(trd + kb * 64);
            float2 p1 = lds_v2(trd + kb * 64 + 32);
            ss += p0.x * p0.x + p0.y * p0.y + p1.x * p1.x + p1.y * p1.y;
            af0[kb] = pack_h2(p0.x, p0.y);
            af1[kb] = pack_h2(p1.x, p1.y);
        }
        // row norm: 4 lanes (same lane>>2) hold disjoint 32-col partials
        ss += __shfl_xor_sync(0xFFFFFFFFu, ss, 1);
        ss += __shfl_xor_sync(0xFFFFFFFFu, ss, 2);
        const float rn = rsqrtf(fmaxf(ss, 1e-24f));

        __syncwarp();    // all lanes done reading buf before overwrite
        if (t + NSTG < NTILES) {
            const char* g = dbase + (size_t)(t + NSTG) * TILE_M * 512 + g_w_base;
            uint32_t sdst = smS + buf + s_w_base;
            #pragma unroll
            for (int r = 0; r < 8; r++)
                cp_async16(sdst + r * SPITCH, g + r * 512);
        }
        cp_commit();     // unconditional: uniform wait accounting

        // --- HMMA: 8 real doc rows x 32 queries (upper fragment half duplicated) ---
        float acc[4][4];
        #pragma unroll
        for (int n = 0; n < 4; n++)
            #pragma unroll
            for (int i = 0; i < 4; i++) acc[n][i] = 0.f;

        #pragma unroll
        for (int kb = 0; kb < 8; kb++) {
            uint32_t aa[4] = {af0[kb], af0[kb], af1[kb], af1[kb]};
            #pragma unroll
            for (int n = 0; n < 4; n++) mma16816(acc[n], aa, bf[kb][n]);
        }

        // --- epilogue: c0,c1 are this thread's row; scale by 1/||d||, running max ---
        #pragma unroll
        for (int n = 0; n < 4; n++) {
            vmax[n * 2 + 0] = fmaxf(vmax[n * 2 + 0], acc[n][0] * rn);
            vmax[n * 2 + 1] = fmaxf(vmax[n * 2 + 1], acc[n][1] * rn);
        }
    }

    // ---- reduce: max over lanes sharing a query column (xor 4,8,16) ----
    #pragma unroll
    for (int e = 0; e < 8; e++) {
        vmax[e] = fmaxf(vmax[e], __shfl_xor_sync(0xFFFFFFFFu, vmax[e], 4));
        vmax[e] = fmaxf(vmax[e], __shfl_xor_sync(0xFFFFFFFFu, vmax[e], 8));
        vmax[e] = fmaxf(vmax[e], __shfl_xor_sync(0xFFFFFFFFu, vmax[e], 16));
    }
    if (lane < 4) {
        #pragma unroll
        for (int e = 0; e < 8; e++) {
            int col = (e >> 1) * 8 + lane * 2 + (e & 1);
            red[w * 32 + col] = vmax[e];
        }
    }
    __syncthreads();
    if (tid < 32) {
        float m = red[tid];
        #pragma unroll
        for (int ww = 1; ww < NW; ww++) m = fmaxf(m, red[ww * 32 + tid]);
        #pragma unroll
        for (int o = 16; o; o >>= 1) m += __shfl_xor_sync(0xFFFFFFFFu, m, o);
        if (tid == 0) out[b] = m;
    }
}

// ---------------- host launch ----------------
extern "C" void kernel_launch(void* const* d_in, const int* in_sizes, int n_in,
                              void* d_out, int out_size) {
    const float* q   = (const float*)d_in[0];   // [1024, 32, 128] f32
    const float* doc = (const float*)d_in[1];   // [1024, 2048, 128] f32
    float* out = (float*)d_out;                 // [1024] f32

    cudaFuncSetAttribute(maxsim_kernel,
                         cudaFuncAttributeMaxDynamicSharedMemorySize, SMEM_TOTAL);

    maxsim_kernel<<<NB, NT, SMEM_TOTAL>>>(q, doc, out);
}